// round 11
// baseline (speedup 1.0000x reference)
#include <cuda_runtime.h>

// Problem constants: K=2 speakers, M=2 masks, T=3000, F=513, D=6
#define KF   513
#define TT   3000
#define TFE  (TT*KF)          // 1,539,000
#define NCHUNK 30
#define CHUNK  (TT/NCHUNK)    // 100
#define SLAB  10              // t-slab staged in shared memory

#define GPART_N (NCHUNK*4*42*KF)   // 2,585,520 floats
#define GW_N    (2*KF*12)          // 12,312 floats (49 KB)

// Scratch layout inside d_out (floats). d_out = out_size = 2*TFE = 3,078,000
// float32 elements (CONFIRMED R10: literal guard stopped the fault).
// PART+PSD end = 2,733,264 < 3,078,000; apply overwrites [0, 2*TFE) fully.
#define PART_OFF 0
#define PSD_OFF  GPART_N           // 2,585,520

// Only static device scratch: 49 KB weights (stub-sanctioned size class).
__device__ float g_w[GW_N];

__device__ __forceinline__ int iclamp(int i, int n) { return i < n ? (i < 0 ? 0 : i) : n - 1; }

// ---------------------------------------------------------------------------
// Kernel 1 (smem-staged): mask-weighted PSD partials per t-chunk.
// ---------------------------------------------------------------------------
__global__ __launch_bounds__(128) void psd_partial_kernel(
    const float* __restrict__ masks,
    const float* __restrict__ Or,
    const float* __restrict__ Oi,
    float* __restrict__ sc, int sc_n,
    int masks_n, int obs_n)
{
    __shared__ float s_m [4][SLAB][32];
    __shared__ float s_or[6][SLAB][32];
    __shared__ float s_oi[6][SLAB][32];

    int tid  = threadIdx.x;
    int lane = tid & 31;
    int km   = tid >> 5;               // 0..3
    int f0   = blockIdx.x * 32;
    int f    = f0 + lane;
    int c    = blockIdx.y;             // t-chunk

    float accR[21], accI[21];
#pragma unroll
    for (int p = 0; p < 21; p++) { accR[p] = 0.f; accI[p] = 0.f; }

    for (int s = 0; s < CHUNK / SLAB; s++) {
        int tg = c * CHUNK + s * SLAB;     // global t of slab start
        for (int idx = tid; idx < 4 * SLAB * 32; idx += 128) {
            int pl = idx / (SLAB * 32);
            int rm = idx - pl * (SLAB * 32);
            int tt = rm >> 5;
            int fi = rm & 31;
            s_m[pl][tt][fi] = masks[iclamp(pl * TFE + (tg + tt) * KF + f0 + fi, masks_n)];
        }
        for (int idx = tid; idx < 6 * SLAB * 32; idx += 128) {
            int pl = idx / (SLAB * 32);
            int rm = idx - pl * (SLAB * 32);
            int tt = rm >> 5;
            int fi = rm & 31;
            int gi = iclamp(pl * TFE + (tg + tt) * KF + f0 + fi, obs_n);
            s_or[pl][tt][fi] = Or[gi];
            s_oi[pl][tt][fi] = Oi[gi];
        }
        __syncthreads();
        if (f < KF) {
#pragma unroll 2
            for (int tt = 0; tt < SLAB; tt++) {
                float mk = s_m[km][tt][lane];
                float vr[6], vi[6];
#pragma unroll
                for (int d = 0; d < 6; d++) {
                    vr[d] = s_or[d][tt][lane];
                    vi[d] = s_oi[d][tt][lane];
                }
                int p = 0;
#pragma unroll
                for (int d = 0; d < 6; d++) {
                    float mr = mk * vr[d];
                    float mi = mk * vi[d];
#pragma unroll
                    for (int D = d; D < 6; D++) {
                        accR[p] += mr * vr[D] + mi * vi[D];   // m * v_d * conj(v_D)
                        accI[p] += mi * vr[D] - mr * vi[D];
                        p++;
                    }
                }
            }
        }
        __syncthreads();
    }

    if (f < KF) {
        int obase = PART_OFF + (c * 4 + km) * 42 * KF + f;
#pragma unroll
        for (int p = 0; p < 21; p++) {
            int i0 = obase + (2 * p) * KF;
            int i1 = obase + (2 * p + 1) * KF;
            if (i0 >= 0 && i0 < sc_n) sc[i0] = accR[p];
            if (i1 >= 0 && i1 < sc_n) sc[i1] = accI[p];
        }
    }
}

// ---------------------------------------------------------------------------
// Kernel 2: deterministic ordered reduction over chunks; expand Hermitian.
// ---------------------------------------------------------------------------
__global__ __launch_bounds__(128) void psd_reduce_kernel(
    float* __restrict__ sc, int sc_n)
{
    int f = blockIdx.y * 128 + threadIdx.x;
    if (f >= KF) return;
    int kmj = blockIdx.x;                 // 0..167
    int km  = kmj / 42;
    int j   = kmj - km * 42;

    float s = 0.f;
    for (int cc = 0; cc < NCHUNK; cc++)
        s += sc[iclamp(PART_OFF + ((cc * 4 + km) * 42 + j) * KF + f, sc_n)];

    int p  = j >> 1;
    int ri = j & 1;
    int d = 0, q = p;                     // upper-tri pair p -> (d,D)
    while (q >= 6 - d) { q -= 6 - d; d++; }
    int D = d + q;

    int base = PSD_OFF + (km * KF + f) * 72;
    int i0 = base + (d * 6 + D) * 2 + ri;
    if (i0 >= 0 && i0 < sc_n) sc[i0] = s;
    if (d != D) {
        int i1 = base + (D * 6 + d) * 2 + ri;
        if (i1 >= 0 && i1 < sc_n) sc[i1] = ri ? -s : s;   // Hermitian mirror
    }
}

// ---------------------------------------------------------------------------
// Kernel 3: stack-free warp-parallel fp32 Gauss-Jordan in shared memory.
// Two explicit scalar element-slots per lane; no runtime-indexed local arrays.
// ---------------------------------------------------------------------------
__global__ __launch_bounds__(128) void solve_kernel_ws(
    const float* __restrict__ sc, int sc_n)
{
    __shared__ float sAr[4][36], sAi[4][36], sBr[4][36], sBi[4][36];
    int w    = threadIdx.x >> 5;
    int lane = threadIdx.x & 31;
    int idx  = blockIdx.x * 4 + w;        // (k,f) system id
    if (idx >= 2 * KF) return;            // whole warp exits together
    int k = idx / KF;
    int f = idx - k * KF;

    int  l0 = lane;                       // element slot 0 (always < 36)
    int  l1 = lane + 32;                  // element slot 1 (valid if lane < 4)
    bool h1 = lane < 4;
    int  r0 = l0 / 6, e0 = l0 - 6 * r0;
    int  r1 = l1 / 6, e1 = l1 - 6 * r1;   // only used when h1

    int aBase = PSD_OFF + ((k * 2 + 1) * KF + f) * 72;  // interference (m=1)
    int bBase = PSD_OFF + ((k * 2 + 0) * KF + f) * 72;  // target (m=0)
    sAr[w][l0] = sc[iclamp(aBase + 2 * l0,     sc_n)];
    sAi[w][l0] = sc[iclamp(aBase + 2 * l0 + 1, sc_n)];
    sBr[w][l0] = sc[iclamp(bBase + 2 * l0,     sc_n)];
    sBi[w][l0] = sc[iclamp(bBase + 2 * l0 + 1, sc_n)];
    if (h1) {
        sAr[w][l1] = sc[iclamp(aBase + 2 * l1,     sc_n)];
        sAi[w][l1] = sc[iclamp(aBase + 2 * l1 + 1, sc_n)];
        sBr[w][l1] = sc[iclamp(bBase + 2 * l1,     sc_n)];
        sBi[w][l1] = sc[iclamp(bBase + 2 * l1 + 1, sc_n)];
    }
    __syncwarp();

#pragma unroll
    for (int col = 0; col < 6; col++) {
        float pr  = sAr[w][col * 7], pi = sAi[w][col * 7];
        float inv = 1.f / (pr * pr + pi * pi);
        float srr =  pr * inv;
        float sii = -pi * inv;
        __syncwarp();
        if (r0 == col) {
            float ar = sAr[w][l0], ai = sAi[w][l0];
            sAr[w][l0] = ar * srr - ai * sii;
            sAi[w][l0] = ar * sii + ai * srr;
            float br = sBr[w][l0], bi = sBi[w][l0];
            sBr[w][l0] = br * srr - bi * sii;
            sBi[w][l0] = br * sii + bi * srr;
        }
        if (h1 && r1 == col) {
            float ar = sAr[w][l1], ai = sAi[w][l1];
            sAr[w][l1] = ar * srr - ai * sii;
            sAi[w][l1] = ar * sii + ai * srr;
            float br = sBr[w][l1], bi = sBi[w][l1];
            sBr[w][l1] = br * srr - bi * sii;
            sBi[w][l1] = br * sii + bi * srr;
        }
        __syncwarp();
        float f0r = 0.f, f0i = 0.f, p0r = 0.f, p0i = 0.f, q0r = 0.f, q0i = 0.f;
        if (r0 != col) {
            f0r = sAr[w][r0 * 6 + col];  f0i = sAi[w][r0 * 6 + col];
            p0r = sAr[w][col * 6 + e0];  p0i = sAi[w][col * 6 + e0];
            q0r = sBr[w][col * 6 + e0];  q0i = sBi[w][col * 6 + e0];
        }
        float f1r = 0.f, f1i = 0.f, p1r = 0.f, p1i = 0.f, q1r = 0.f, q1i = 0.f;
        if (h1 && r1 != col) {
            f1r = sAr[w][r1 * 6 + col];  f1i = sAi[w][r1 * 6 + col];
            p1r = sAr[w][col * 6 + e1];  p1i = sAi[w][col * 6 + e1];
            q1r = sBr[w][col * 6 + e1];  q1i = sBi[w][col * 6 + e1];
        }
        __syncwarp();
        if (r0 != col) {
            sAr[w][l0] -= f0r * p0r - f0i * p0i;
            sAi[w][l0] -= f0r * p0i + f0i * p0r;
            sBr[w][l0] -= f0r * q0r - f0i * q0i;
            sBi[w][l0] -= f0r * q0i + f0i * q0r;
        }
        if (h1 && r1 != col) {
            sAr[w][l1] -= f1r * p1r - f1i * p1i;
            sAi[w][l1] -= f1r * p1i + f1i * p1r;
            sBr[w][l1] -= f1r * q1r - f1i * q1i;
            sBi[w][l1] -= f1r * q1i + f1i * q1r;
        }
        __syncwarp();
    }

    float trr = sBr[w][0] + sBr[w][7] + sBr[w][14] +
                sBr[w][21] + sBr[w][28] + sBr[w][35];
    const float tinyf = 1.17549435e-38f;
    float lam  = trr < tinyf ? tinyf : trr;
    float invl = 1.f / lam;

    if (e0 == 0) {                        // lanes 0,6,12,18,24,30 own phi[r][0]
        int wB = (k * KF + f) * 12 + 2 * r0;
        if (wB >= 0 && wB + 1 < GW_N) {
            g_w[wB]     =  sBr[w][l0] * invl;   // conj(beamformer)
            g_w[wB + 1] = -sBi[w][l0] * invl;
        }
    }
}

// ---------------------------------------------------------------------------
// Kernel 4: enh[k,t,f] = sum_d W[k,f,d] * Obs[d,t,f]  (W pre-conjugated).
// OUTPUT = REAL PART ONLY, float32 [k,t,f] (the numpy float32 cast of the
// complex reference -- matches out_size = 2*TFE exactly).
// ---------------------------------------------------------------------------
__global__ __launch_bounds__(256) void apply_kernel(
    const float* __restrict__ Or,
    const float* __restrict__ Oi,
    float* __restrict__ out,
    int obs_n, int out_floats)
{
    int i = blockIdx.x * 256 + threadIdx.x;
    if (i >= TFE) return;
    int f = i % KF;

    float vr[6], vi[6];
#pragma unroll
    for (int d = 0; d < 6; d++) {
        int oidx = iclamp(d * TFE + i, obs_n);
        vr[d] = Or[oidx];
        vi[d] = Oi[oidx];
    }
#pragma unroll
    for (int k = 0; k < 2; k++) {
        int wBase = (k * KF + f) * 12;
        float er = 0.f;
#pragma unroll
        for (int d = 0; d < 6; d++) {
            float wr = g_w[iclamp(wBase + 2 * d,     GW_N)];
            float wi = g_w[iclamp(wBase + 2 * d + 1, GW_N)];
            // Re( w * (vr + i vi) ) with w = wr + i wi (pre-conjugated)
            er = fmaf(wr, vr[d], fmaf(-wi, vi[d], er));
        }
        int o = k * TFE + i;              // [k,t,f] float32 layout
        if (o >= 0 && o < out_floats) out[o] = er;
    }
}

// ---------------------------------------------------------------------------
extern "C" void kernel_launch(void* const* d_in, const int* in_sizes, int n_in,
                              void* d_out, int out_size)
{
    // Bind by element count: masks=4*TFE; the two 6*TFE buffers are Obs_real
    // then Obs_imag in declaration order; the scalar input is ignored.
    const float* masks = 0;
    const float* Or    = 0;
    const float* Oi    = 0;
    int masks_n = 0, obs_n = 0;
    for (int i = 0; i < n_in; i++) {
        int sz = in_sizes[i];
        if (sz == 4 * TFE) {
            masks = (const float*)d_in[i]; masks_n = sz;
        } else if (sz == 6 * TFE) {
            if (!Or) { Or = (const float*)d_in[i]; obs_n = sz; }
            else if (!Oi) Oi = (const float*)d_in[i];
        }
    }
    if (!masks || !Or || !Oi || !d_out) return;

    // out_size is LITERAL: 2*TFE float32 elements (confirmed R10).
    int out_floats = out_size;
    float* sc = (float*)d_out;            // scratch lives inside d_out

    dim3 g1((KF + 31) / 32, NCHUNK);
    psd_partial_kernel<<<g1, 128>>>(masks, Or, Oi, sc, out_floats,
                                    masks_n, obs_n);

    dim3 g2(4 * 42, (KF + 127) / 128);
    psd_reduce_kernel<<<g2, 128>>>(sc, out_floats);

    solve_kernel_ws<<<(2 * KF + 3) / 4, 128>>>(sc, out_floats);

    apply_kernel<<<(TFE + 255) / 256, 256>>>(Or, Oi, (float*)d_out,
                                             obs_n, out_floats);
}

// round 12
// speedup vs baseline: 1.7344x; 1.7344x over previous
#include <cuda_runtime.h>

// Problem constants: K=2 speakers, M=2 masks, T=3000, F=513, D=6
#define KF   513
#define TT   3000
#define TFE  (TT*KF)          // 1,539,000
#define NCHUNK 30
#define CHUNK  (TT/NCHUNK)    // 100
#define SLAB  4               // t-rows per pipeline stage (= warps/block)
#define NSLAB (CHUNK/SLAB)    // 25
#define T_TILE 25             // apply: t-rows per block

#define GPART_N (NCHUNK*4*42*KF)   // 2,585,520 floats
#define GW_N    (2*KF*12)          // 12,312 floats (49 KB)

// Scratch layout inside d_out (floats). d_out = out_size = 2*TFE = 3,078,000
// float32 elements (confirmed R10/R11). PART+PSD end = 2,733,264 < 2*TFE;
// apply overwrites [0, 2*TFE) fully afterwards.
#define PART_OFF 0
#define PSD_OFF  GPART_N           // 2,585,520

// Only static device scratch: 49 KB weights (proven safe R10/R11).
__device__ float g_w[GW_N];

__device__ __forceinline__ int iclamp(int i, int n) { return i < n ? (i < 0 ? 0 : i) : n - 1; }

// ---------------------------------------------------------------------------
// Kernel 1: mask-weighted PSD partials, double-buffered smem pipeline.
// Block = 128 = 4 warps; warp w loads t-row tt=w of each plane and computes
// km=w for 32 f's. Per stage: issue 16 LDG -> regs, compute current buffer,
// commit regs -> other buffer, sync. DRAM latency hides under compute.
// ---------------------------------------------------------------------------
__global__ __launch_bounds__(128) void psd_partial_kernel(
    const float* __restrict__ masks,
    const float* __restrict__ Or,
    const float* __restrict__ Oi,
    float* __restrict__ sc, int sc_n,
    int masks_n, int obs_n)
{
    __shared__ float s_m [2][4][SLAB][32];   // [buf][plane][tt][fi] 4 KB
    __shared__ float s_or[2][6][SLAB][32];   // 6 KB
    __shared__ float s_oi[2][6][SLAB][32];   // 6 KB

    int tid  = threadIdx.x;
    int lane = tid & 31;
    int km   = tid >> 5;               // 0..3 : warp id = km = loaded t-row
    int f0   = blockIdx.x * 32;
    int f    = f0 + lane;
    int c    = blockIdx.y;             // t-chunk

    // Fixed per-thread base offsets (addr = base + tg*KF each stage)
    int baseM0 = 0 * TFE + km * KF + f;
    int baseM1 = 1 * TFE + km * KF + f;
    int baseM2 = 2 * TFE + km * KF + f;
    int baseM3 = 3 * TFE + km * KF + f;
    int baseO0 = 0 * TFE + km * KF + f;
    int baseO1 = 1 * TFE + km * KF + f;
    int baseO2 = 2 * TFE + km * KF + f;
    int baseO3 = 3 * TFE + km * KF + f;
    int baseO4 = 4 * TFE + km * KF + f;
    int baseO5 = 5 * TFE + km * KF + f;

    float accR[21], accI[21];
#pragma unroll
    for (int p = 0; p < 21; p++) { accR[p] = 0.f; accI[p] = 0.f; }

    float rm0, rm1, rm2, rm3;
    float ro0, ro1, ro2, ro3, ro4, ro5;
    float rj0, rj1, rj2, rj3, rj4, rj5;

#define ISSUE(S) do { int tg = (c * CHUNK + (S) * SLAB) * KF;                 \
        rm0 = masks[iclamp(baseM0 + tg, masks_n)];                            \
        rm1 = masks[iclamp(baseM1 + tg, masks_n)];                            \
        rm2 = masks[iclamp(baseM2 + tg, masks_n)];                            \
        rm3 = masks[iclamp(baseM3 + tg, masks_n)];                            \
        ro0 = Or[iclamp(baseO0 + tg, obs_n)];  rj0 = Oi[iclamp(baseO0 + tg, obs_n)]; \
        ro1 = Or[iclamp(baseO1 + tg, obs_n)];  rj1 = Oi[iclamp(baseO1 + tg, obs_n)]; \
        ro2 = Or[iclamp(baseO2 + tg, obs_n)];  rj2 = Oi[iclamp(baseO2 + tg, obs_n)]; \
        ro3 = Or[iclamp(baseO3 + tg, obs_n)];  rj3 = Oi[iclamp(baseO3 + tg, obs_n)]; \
        ro4 = Or[iclamp(baseO4 + tg, obs_n)];  rj4 = Oi[iclamp(baseO4 + tg, obs_n)]; \
        ro5 = Or[iclamp(baseO5 + tg, obs_n)];  rj5 = Oi[iclamp(baseO5 + tg, obs_n)]; \
    } while (0)

#define COMMIT(B) do {                                                        \
        s_m [B][0][km][lane] = rm0;  s_m [B][1][km][lane] = rm1;              \
        s_m [B][2][km][lane] = rm2;  s_m [B][3][km][lane] = rm3;              \
        s_or[B][0][km][lane] = ro0;  s_oi[B][0][km][lane] = rj0;              \
        s_or[B][1][km][lane] = ro1;  s_oi[B][1][km][lane] = rj1;              \
        s_or[B][2][km][lane] = ro2;  s_oi[B][2][km][lane] = rj2;              \
        s_or[B][3][km][lane] = ro3;  s_oi[B][3][km][lane] = rj3;              \
        s_or[B][4][km][lane] = ro4;  s_oi[B][4][km][lane] = rj4;              \
        s_or[B][5][km][lane] = ro5;  s_oi[B][5][km][lane] = rj5;              \
    } while (0)

    ISSUE(0);
    COMMIT(0);
    __syncthreads();

    for (int s = 0; s < NSLAB; s++) {
        if (s + 1 < NSLAB) ISSUE(s + 1);       // LDGs in flight during compute
        int b = s & 1;
#pragma unroll
        for (int tt = 0; tt < SLAB; tt++) {
            float mk = s_m[b][km][tt][lane];
            float vr[6], vi[6];
#pragma unroll
            for (int d = 0; d < 6; d++) {
                vr[d] = s_or[b][d][tt][lane];
                vi[d] = s_oi[b][d][tt][lane];
            }
            int p = 0;
#pragma unroll
            for (int d = 0; d < 6; d++) {
                float mr = mk * vr[d];
                float mi = mk * vi[d];
#pragma unroll
                for (int D = d; D < 6; D++) {
                    accR[p] += mr * vr[D] + mi * vi[D];   // m * v_d * conj(v_D)
                    accI[p] += mi * vr[D] - mr * vi[D];
                    p++;
                }
            }
        }
        if (s + 1 < NSLAB) COMMIT((s + 1) & 1);
        __syncthreads();
    }
#undef ISSUE
#undef COMMIT

    if (f < KF) {
        int obase = PART_OFF + (c * 4 + km) * 42 * KF + f;
#pragma unroll
        for (int p = 0; p < 21; p++) {
            int i0 = obase + (2 * p) * KF;
            int i1 = obase + (2 * p + 1) * KF;
            if (i0 >= 0 && i0 < sc_n) sc[i0] = accR[p];
            if (i1 >= 0 && i1 < sc_n) sc[i1] = accI[p];
        }
    }
}

// ---------------------------------------------------------------------------
// Kernel 2: deterministic ordered reduction over chunks; expand Hermitian.
// ---------------------------------------------------------------------------
__global__ __launch_bounds__(128) void psd_reduce_kernel(
    float* __restrict__ sc, int sc_n)
{
    int f = blockIdx.y * 128 + threadIdx.x;
    if (f >= KF) return;
    int kmj = blockIdx.x;                 // 0..167
    int km  = kmj / 42;
    int j   = kmj - km * 42;

    float s = 0.f;
    for (int cc = 0; cc < NCHUNK; cc++)
        s += sc[iclamp(PART_OFF + ((cc * 4 + km) * 42 + j) * KF + f, sc_n)];

    int p  = j >> 1;
    int ri = j & 1;
    int d = 0, q = p;                     // upper-tri pair p -> (d,D)
    while (q >= 6 - d) { q -= 6 - d; d++; }
    int D = d + q;

    int base = PSD_OFF + (km * KF + f) * 72;
    int i0 = base + (d * 6 + D) * 2 + ri;
    if (i0 >= 0 && i0 < sc_n) sc[i0] = s;
    if (d != D) {
        int i1 = base + (D * 6 + d) * 2 + ri;
        if (i1 >= 0 && i1 < sc_n) sc[i1] = ri ? -s : s;   // Hermitian mirror
    }
}

// ---------------------------------------------------------------------------
// Kernel 3: stack-free warp-parallel fp32 Gauss-Jordan in shared memory.
// ---------------------------------------------------------------------------
__global__ __launch_bounds__(128) void solve_kernel_ws(
    const float* __restrict__ sc, int sc_n)
{
    __shared__ float sAr[4][36], sAi[4][36], sBr[4][36], sBi[4][36];
    int w    = threadIdx.x >> 5;
    int lane = threadIdx.x & 31;
    int idx  = blockIdx.x * 4 + w;        // (k,f) system id
    if (idx >= 2 * KF) return;            // whole warp exits together
    int k = idx / KF;
    int f = idx - k * KF;

    int  l0 = lane;
    int  l1 = lane + 32;
    bool h1 = lane < 4;
    int  r0 = l0 / 6, e0 = l0 - 6 * r0;
    int  r1 = l1 / 6, e1 = l1 - 6 * r1;

    int aBase = PSD_OFF + ((k * 2 + 1) * KF + f) * 72;  // interference (m=1)
    int bBase = PSD_OFF + ((k * 2 + 0) * KF + f) * 72;  // target (m=0)
    sAr[w][l0] = sc[iclamp(aBase + 2 * l0,     sc_n)];
    sAi[w][l0] = sc[iclamp(aBase + 2 * l0 + 1, sc_n)];
    sBr[w][l0] = sc[iclamp(bBase + 2 * l0,     sc_n)];
    sBi[w][l0] = sc[iclamp(bBase + 2 * l0 + 1, sc_n)];
    if (h1) {
        sAr[w][l1] = sc[iclamp(aBase + 2 * l1,     sc_n)];
        sAi[w][l1] = sc[iclamp(aBase + 2 * l1 + 1, sc_n)];
        sBr[w][l1] = sc[iclamp(bBase + 2 * l1,     sc_n)];
        sBi[w][l1] = sc[iclamp(bBase + 2 * l1 + 1, sc_n)];
    }
    __syncwarp();

#pragma unroll
    for (int col = 0; col < 6; col++) {
        float pr  = sAr[w][col * 7], pi = sAi[w][col * 7];
        float inv = 1.f / (pr * pr + pi * pi);
        float srr =  pr * inv;
        float sii = -pi * inv;
        __syncwarp();
        if (r0 == col) {
            float ar = sAr[w][l0], ai = sAi[w][l0];
            sAr[w][l0] = ar * srr - ai * sii;
            sAi[w][l0] = ar * sii + ai * srr;
            float br = sBr[w][l0], bi = sBi[w][l0];
            sBr[w][l0] = br * srr - bi * sii;
            sBi[w][l0] = br * sii + bi * srr;
        }
        if (h1 && r1 == col) {
            float ar = sAr[w][l1], ai = sAi[w][l1];
            sAr[w][l1] = ar * srr - ai * sii;
            sAi[w][l1] = ar * sii + ai * srr;
            float br = sBr[w][l1], bi = sBi[w][l1];
            sBr[w][l1] = br * srr - bi * sii;
            sBi[w][l1] = br * sii + bi * srr;
        }
        __syncwarp();
        float f0r = 0.f, f0i = 0.f, p0r = 0.f, p0i = 0.f, q0r = 0.f, q0i = 0.f;
        if (r0 != col) {
            f0r = sAr[w][r0 * 6 + col];  f0i = sAi[w][r0 * 6 + col];
            p0r = sAr[w][col * 6 + e0];  p0i = sAi[w][col * 6 + e0];
            q0r = sBr[w][col * 6 + e0];  q0i = sBi[w][col * 6 + e0];
        }
        float f1r = 0.f, f1i = 0.f, p1r = 0.f, p1i = 0.f, q1r = 0.f, q1i = 0.f;
        if (h1 && r1 != col) {
            f1r = sAr[w][r1 * 6 + col];  f1i = sAi[w][r1 * 6 + col];
            p1r = sAr[w][col * 6 + e1];  p1i = sAi[w][col * 6 + e1];
            q1r = sBr[w][col * 6 + e1];  q1i = sBi[w][col * 6 + e1];
        }
        __syncwarp();
        if (r0 != col) {
            sAr[w][l0] -= f0r * p0r - f0i * p0i;
            sAi[w][l0] -= f0r * p0i + f0i * p0r;
            sBr[w][l0] -= f0r * q0r - f0i * q0i;
            sBi[w][l0] -= f0r * q0i + f0i * q0r;
        }
        if (h1 && r1 != col) {
            sAr[w][l1] -= f1r * p1r - f1i * p1i;
            sAi[w][l1] -= f1r * p1i + f1i * p1r;
            sBr[w][l1] -= f1r * q1r - f1i * q1i;
            sBi[w][l1] -= f1r * q1i + f1i * q1r;
        }
        __syncwarp();
    }

    float trr = sBr[w][0] + sBr[w][7] + sBr[w][14] +
                sBr[w][21] + sBr[w][28] + sBr[w][35];
    const float tinyf = 1.17549435e-38f;
    float lam  = trr < tinyf ? tinyf : trr;
    float invl = 1.f / lam;

    if (e0 == 0) {                        // lanes 0,6,12,18,24,30 own phi[r][0]
        int wB = (k * KF + f) * 12 + 2 * r0;
        if (wB >= 0 && wB + 1 < GW_N) {
            g_w[wB]     =  sBr[w][l0] * invl;   // conj(beamformer)
            g_w[wB + 1] = -sBi[w][l0] * invl;
        }
    }
}

// ---------------------------------------------------------------------------
// Kernel 4 (TILED): enh real part. Block = 128 f-lanes x T_TILE t-rows.
// Weights loaded ONCE per thread into registers (amortized over T_TILE),
// then per t: 12 coalesced loads + 2 coalesced stores. Kills the stride-12
// per-t g_w traffic that made R11's apply L1-bound (74.5% L1, 35% DRAM).
// ---------------------------------------------------------------------------
__global__ __launch_bounds__(128) void apply_kernel(
    const float* __restrict__ Or,
    const float* __restrict__ Oi,
    float* __restrict__ out,
    int obs_n, int out_floats)
{
    int f  = blockIdx.x * 128 + threadIdx.x;
    int t0 = blockIdx.y * T_TILE;
    if (f >= KF) return;

    float w0r[6], w0i[6], w1r[6], w1i[6];
#pragma unroll
    for (int d = 0; d < 6; d++) {
        w0r[d] = g_w[iclamp((0 * KF + f) * 12 + 2 * d,     GW_N)];
        w0i[d] = g_w[iclamp((0 * KF + f) * 12 + 2 * d + 1, GW_N)];
        w1r[d] = g_w[iclamp((1 * KF + f) * 12 + 2 * d,     GW_N)];
        w1i[d] = g_w[iclamp((1 * KF + f) * 12 + 2 * d + 1, GW_N)];
    }

    for (int t = t0; t < t0 + T_TILE; t++) {
        int i = t * KF + f;
        float vr[6], vi[6];
#pragma unroll
        for (int d = 0; d < 6; d++) {
            int oidx = iclamp(d * TFE + i, obs_n);
            vr[d] = Or[oidx];
            vi[d] = Oi[oidx];
        }
        float e0 = 0.f, e1 = 0.f;
#pragma unroll
        for (int d = 0; d < 6; d++) {
            e0 = fmaf(w0r[d], vr[d], fmaf(-w0i[d], vi[d], e0));
            e1 = fmaf(w1r[d], vr[d], fmaf(-w1i[d], vi[d], e1));
        }
        if (i >= 0 && i < out_floats)             out[i]       = e0;
        if (TFE + i >= 0 && TFE + i < out_floats) out[TFE + i] = e1;
    }
}

// ---------------------------------------------------------------------------
extern "C" void kernel_launch(void* const* d_in, const int* in_sizes, int n_in,
                              void* d_out, int out_size)
{
    const float* masks = 0;
    const float* Or    = 0;
    const float* Oi    = 0;
    int masks_n = 0, obs_n = 0;
    for (int i = 0; i < n_in; i++) {
        int sz = in_sizes[i];
        if (sz == 4 * TFE) {
            masks = (const float*)d_in[i]; masks_n = sz;
        } else if (sz == 6 * TFE) {
            if (!Or) { Or = (const float*)d_in[i]; obs_n = sz; }
            else if (!Oi) Oi = (const float*)d_in[i];
        }
    }
    if (!masks || !Or || !Oi || !d_out) return;

    int out_floats = out_size;            // literal float32 element count
    float* sc = (float*)d_out;            // scratch lives inside d_out

    dim3 g1((KF + 31) / 32, NCHUNK);
    psd_partial_kernel<<<g1, 128>>>(masks, Or, Oi, sc, out_floats,
                                    masks_n, obs_n);

    dim3 g2(4 * 42, (KF + 127) / 128);
    psd_reduce_kernel<<<g2, 128>>>(sc, out_floats);

    solve_kernel_ws<<<(2 * KF + 3) / 4, 128>>>(sc, out_floats);

    dim3 g4((KF + 127) / 128, TT / T_TILE);
    apply_kernel<<<g4, 128>>>(Or, Oi, (float*)d_out, obs_n, out_floats);
}

// round 13
// speedup vs baseline: 1.9810x; 1.1421x over previous
#include <cuda_runtime.h>

// Problem constants: K=2 speakers, M=2 masks, T=3000, F=513, D=6
#define KF   513
#define TT   3000
#define TFE  (TT*KF)          // 1,539,000
#define NCHUNK 75
#define CHUNK  (TT/NCHUNK)    // 40
#define SLAB  4               // t-rows per pipeline stage (= warps/block)
#define NSLAB (CHUNK/SLAB)    // 10
#define T_TILE 4              // apply: t-rows per block

#define GPART_N (NCHUNK*4*42*KF)   // 6,463,800 floats (25.9 MB)
#define GPSD_N  (4*KF*72)          // 147,744 floats
#define GW_N    (2*KF*12)          // 12,312 floats

// Device-global scratch (R6+R10 established globals are safe; the historic
// fault was the d_out guard). No scratch in d_out anymore.
__device__ float g_part[GPART_N];
__device__ float g_psd[GPSD_N];
__device__ float g_w[GW_N];

// ---------------------------------------------------------------------------
// Kernel 1: mask-weighted PSD partials, double-buffered smem pipeline.
// Block = 128 = 4 warps; warp w loads t-row tt=w of all 16 planes, computes
// km=w for 32 f's. Diagonal imag accumulators (identically 0) elided.
// ---------------------------------------------------------------------------
__global__ __launch_bounds__(128) void psd_partial_kernel(
    const float* __restrict__ masks,
    const float* __restrict__ Or,
    const float* __restrict__ Oi)
{
    __shared__ float s_m [2][4][SLAB][32];
    __shared__ float s_or[2][6][SLAB][32];
    __shared__ float s_oi[2][6][SLAB][32];

    int tid  = threadIdx.x;
    int lane = tid & 31;
    int km   = tid >> 5;               // 0..3 : warp id = loaded t-row
    int f0   = blockIdx.x * 32;
    int f    = f0 + lane;
    int fc   = f < KF ? f : KF - 1;    // clamped column for edge tile loads
    int c    = blockIdx.y;             // t-chunk

    int base = km * KF + fc;           // addr = plane*TFE + base + tg*KF

    float accR[21], accI[21];
#pragma unroll
    for (int p = 0; p < 21; p++) { accR[p] = 0.f; accI[p] = 0.f; }

    float rm0, rm1, rm2, rm3;
    float ro0, ro1, ro2, ro3, ro4, ro5;
    float rj0, rj1, rj2, rj3, rj4, rj5;

#define ISSUE(S) do { int tg = (c * CHUNK + (S) * SLAB) * KF + base;          \
        rm0 = masks[0 * TFE + tg];  rm1 = masks[1 * TFE + tg];                \
        rm2 = masks[2 * TFE + tg];  rm3 = masks[3 * TFE + tg];                \
        ro0 = Or[0 * TFE + tg];  rj0 = Oi[0 * TFE + tg];                      \
        ro1 = Or[1 * TFE + tg];  rj1 = Oi[1 * TFE + tg];                      \
        ro2 = Or[2 * TFE + tg];  rj2 = Oi[2 * TFE + tg];                      \
        ro3 = Or[3 * TFE + tg];  rj3 = Oi[3 * TFE + tg];                      \
        ro4 = Or[4 * TFE + tg];  rj4 = Oi[4 * TFE + tg];                      \
        ro5 = Or[5 * TFE + tg];  rj5 = Oi[5 * TFE + tg];                      \
    } while (0)

#define COMMIT(B) do {                                                        \
        s_m [B][0][km][lane] = rm0;  s_m [B][1][km][lane] = rm1;              \
        s_m [B][2][km][lane] = rm2;  s_m [B][3][km][lane] = rm3;              \
        s_or[B][0][km][lane] = ro0;  s_oi[B][0][km][lane] = rj0;              \
        s_or[B][1][km][lane] = ro1;  s_oi[B][1][km][lane] = rj1;              \
        s_or[B][2][km][lane] = ro2;  s_oi[B][2][km][lane] = rj2;              \
        s_or[B][3][km][lane] = ro3;  s_oi[B][3][km][lane] = rj3;              \
        s_or[B][4][km][lane] = ro4;  s_oi[B][4][km][lane] = rj4;              \
        s_or[B][5][km][lane] = ro5;  s_oi[B][5][km][lane] = rj5;              \
    } while (0)

    ISSUE(0);
    COMMIT(0);
    __syncthreads();

    for (int s = 0; s < NSLAB; s++) {
        if (s + 1 < NSLAB) ISSUE(s + 1);       // LDGs in flight during compute
        int b = s & 1;
#pragma unroll
        for (int tt = 0; tt < SLAB; tt++) {
            float mk = s_m[b][km][tt][lane];
            float vr[6], vi[6];
#pragma unroll
            for (int d = 0; d < 6; d++) {
                vr[d] = s_or[b][d][tt][lane];
                vi[d] = s_oi[b][d][tt][lane];
            }
            int p = 0;
#pragma unroll
            for (int d = 0; d < 6; d++) {
                float mr = mk * vr[d];
                float mi = mk * vi[d];
#pragma unroll
                for (int D = d; D < 6; D++) {
                    accR[p] += mr * vr[D] + mi * vi[D];   // m * v_d * conj(v_D)
                    if (D != d)                           // diag imag == 0
                        accI[p] += mi * vr[D] - mr * vi[D];
                    p++;
                }
            }
        }
        if (s + 1 < NSLAB) COMMIT((s + 1) & 1);
        __syncthreads();
    }
#undef ISSUE
#undef COMMIT

    if (f < KF) {
        int obase = (c * 4 + km) * 42 * KF + f;
#pragma unroll
        for (int p = 0; p < 21; p++) {
            g_part[obase + (2 * p)     * KF] = accR[p];
            g_part[obase + (2 * p + 1) * KF] = accI[p];
        }
    }
}

// ---------------------------------------------------------------------------
// Kernel 2: deterministic ordered reduction over chunks; expand Hermitian.
// ---------------------------------------------------------------------------
__global__ __launch_bounds__(128) void psd_reduce_kernel()
{
    int f = blockIdx.y * 128 + threadIdx.x;
    if (f >= KF) return;
    int kmj = blockIdx.x;                 // 0..167
    int km  = kmj / 42;
    int j   = kmj - km * 42;

    float s = 0.f;
    for (int cc = 0; cc < NCHUNK; cc++)
        s += g_part[((cc * 4 + km) * 42 + j) * KF + f];

    int p  = j >> 1;
    int ri = j & 1;
    int d = 0, q = p;                     // upper-tri pair p -> (d,D)
    while (q >= 6 - d) { q -= 6 - d; d++; }
    int D = d + q;

    int base = (km * KF + f) * 72;
    g_psd[base + (d * 6 + D) * 2 + ri] = s;
    if (d != D)
        g_psd[base + (D * 6 + d) * 2 + ri] = ri ? -s : s;   // Hermitian mirror
}

// ---------------------------------------------------------------------------
// Kernel 3: stack-free warp-parallel fp32 Gauss-Jordan in shared memory.
// ---------------------------------------------------------------------------
__global__ __launch_bounds__(128) void solve_kernel_ws()
{
    __shared__ float sAr[4][36], sAi[4][36], sBr[4][36], sBi[4][36];
    int w    = threadIdx.x >> 5;
    int lane = threadIdx.x & 31;
    int idx  = blockIdx.x * 4 + w;        // (k,f) system id
    if (idx >= 2 * KF) return;            // whole warp exits together
    int k = idx / KF;
    int f = idx - k * KF;

    int  l0 = lane;
    int  l1 = lane + 32;
    bool h1 = lane < 4;
    int  r0 = l0 / 6, e0 = l0 - 6 * r0;
    int  r1 = l1 / 6, e1 = l1 - 6 * r1;

    int aBase = ((k * 2 + 1) * KF + f) * 72;  // interference (m=1)
    int bBase = ((k * 2 + 0) * KF + f) * 72;  // target (m=0)
    sAr[w][l0] = g_psd[aBase + 2 * l0];
    sAi[w][l0] = g_psd[aBase + 2 * l0 + 1];
    sBr[w][l0] = g_psd[bBase + 2 * l0];
    sBi[w][l0] = g_psd[bBase + 2 * l0 + 1];
    if (h1) {
        sAr[w][l1] = g_psd[aBase + 2 * l1];
        sAi[w][l1] = g_psd[aBase + 2 * l1 + 1];
        sBr[w][l1] = g_psd[bBase + 2 * l1];
        sBi[w][l1] = g_psd[bBase + 2 * l1 + 1];
    }
    __syncwarp();

#pragma unroll
    for (int col = 0; col < 6; col++) {
        float pr  = sAr[w][col * 7], pi = sAi[w][col * 7];
        float inv = 1.f / (pr * pr + pi * pi);
        float srr =  pr * inv;
        float sii = -pi * inv;
        __syncwarp();
        if (r0 == col) {
            float ar = sAr[w][l0], ai = sAi[w][l0];
            sAr[w][l0] = ar * srr - ai * sii;
            sAi[w][l0] = ar * sii + ai * srr;
            float br = sBr[w][l0], bi = sBi[w][l0];
            sBr[w][l0] = br * srr - bi * sii;
            sBi[w][l0] = br * sii + bi * srr;
        }
        if (h1 && r1 == col) {
            float ar = sAr[w][l1], ai = sAi[w][l1];
            sAr[w][l1] = ar * srr - ai * sii;
            sAi[w][l1] = ar * sii + ai * srr;
            float br = sBr[w][l1], bi = sBi[w][l1];
            sBr[w][l1] = br * srr - bi * sii;
            sBi[w][l1] = br * sii + bi * srr;
        }
        __syncwarp();
        float f0r = 0.f, f0i = 0.f, p0r = 0.f, p0i = 0.f, q0r = 0.f, q0i = 0.f;
        if (r0 != col) {
            f0r = sAr[w][r0 * 6 + col];  f0i = sAi[w][r0 * 6 + col];
            p0r = sAr[w][col * 6 + e0];  p0i = sAi[w][col * 6 + e0];
            q0r = sBr[w][col * 6 + e0];  q0i = sBi[w][col * 6 + e0];
        }
        float f1r = 0.f, f1i = 0.f, p1r = 0.f, p1i = 0.f, q1r = 0.f, q1i = 0.f;
        if (h1 && r1 != col) {
            f1r = sAr[w][r1 * 6 + col];  f1i = sAi[w][r1 * 6 + col];
            p1r = sAr[w][col * 6 + e1];  p1i = sAi[w][col * 6 + e1];
            q1r = sBr[w][col * 6 + e1];  q1i = sBi[w][col * 6 + e1];
        }
        __syncwarp();
        if (r0 != col) {
            sAr[w][l0] -= f0r * p0r - f0i * p0i;
            sAi[w][l0] -= f0r * p0i + f0i * p0r;
            sBr[w][l0] -= f0r * q0r - f0i * q0i;
            sBi[w][l0] -= f0r * q0i + f0i * q0r;
        }
        if (h1 && r1 != col) {
            sAr[w][l1] -= f1r * p1r - f1i * p1i;
            sAi[w][l1] -= f1r * p1i + f1i * p1r;
            sBr[w][l1] -= f1r * q1r - f1i * q1i;
            sBi[w][l1] -= f1r * q1i + f1i * q1r;
        }
        __syncwarp();
    }

    float trr = sBr[w][0] + sBr[w][7] + sBr[w][14] +
                sBr[w][21] + sBr[w][28] + sBr[w][35];
    const float tinyf = 1.17549435e-38f;
    float lam  = trr < tinyf ? tinyf : trr;
    float invl = 1.f / lam;

    if (e0 == 0) {                        // lanes 0,6,12,18,24,30 own phi[r][0]
        int wB = (k * KF + f) * 12 + 2 * r0;
        g_w[wB]     =  sBr[w][l0] * invl;   // conj(beamformer)
        g_w[wB + 1] = -sBi[w][l0] * invl;
    }
}

// ---------------------------------------------------------------------------
// Kernel 4: enh real part, float32 [k,t,f]. Block = 128 f-lanes x 4 t-rows
// (fully unrolled -> 48 independent Obs loads in flight). Grid (5,750) =
// 3750 blocks restores occupancy/MLP that R12's 600-block grid starved.
// ---------------------------------------------------------------------------
__global__ __launch_bounds__(128) void apply_kernel(
    const float* __restrict__ Or,
    const float* __restrict__ Oi,
    float* __restrict__ out,
    int out_floats)
{
    int f  = blockIdx.x * 128 + threadIdx.x;
    int t0 = blockIdx.y * T_TILE;
    if (f >= KF) return;

    float w0r[6], w0i[6], w1r[6], w1i[6];
#pragma unroll
    for (int d = 0; d < 6; d++) {
        w0r[d] = g_w[(0 * KF + f) * 12 + 2 * d];
        w0i[d] = g_w[(0 * KF + f) * 12 + 2 * d + 1];
        w1r[d] = g_w[(1 * KF + f) * 12 + 2 * d];
        w1i[d] = g_w[(1 * KF + f) * 12 + 2 * d + 1];
    }

#pragma unroll
    for (int tt = 0; tt < T_TILE; tt++) {
        int i = (t0 + tt) * KF + f;
        float vr[6], vi[6];
#pragma unroll
        for (int d = 0; d < 6; d++) {
            vr[d] = Or[d * TFE + i];
            vi[d] = Oi[d * TFE + i];
        }
        float e0 = 0.f, e1 = 0.f;
#pragma unroll
        for (int d = 0; d < 6; d++) {
            e0 = fmaf(w0r[d], vr[d], fmaf(-w0i[d], vi[d], e0));
            e1 = fmaf(w1r[d], vr[d], fmaf(-w1i[d], vi[d], e1));
        }
        if (i < out_floats)       out[i]       = e0;
        if (TFE + i < out_floats) out[TFE + i] = e1;
    }
}

// ---------------------------------------------------------------------------
extern "C" void kernel_launch(void* const* d_in, const int* in_sizes, int n_in,
                              void* d_out, int out_size)
{
    const float* masks = 0;
    const float* Or    = 0;
    const float* Oi    = 0;
    for (int i = 0; i < n_in; i++) {
        int sz = in_sizes[i];
        if (sz == 4 * TFE) {
            masks = (const float*)d_in[i];
        } else if (sz == 6 * TFE) {
            if (!Or) Or = (const float*)d_in[i];
            else if (!Oi) Oi = (const float*)d_in[i];
        }
    }
    if (!masks || !Or || !Oi || !d_out) return;

    int out_floats = out_size;            // literal float32 element count

    dim3 g1((KF + 31) / 32, NCHUNK);
    psd_partial_kernel<<<g1, 128>>>(masks, Or, Oi);

    dim3 g2(4 * 42, (KF + 127) / 128);
    psd_reduce_kernel<<<g2, 128>>>();

    solve_kernel_ws<<<(2 * KF + 3) / 4, 128>>>();

    dim3 g4((KF + 127) / 128, TT / T_TILE);
    apply_kernel<<<g4, 128>>>(Or, Oi, (float*)d_out, out_floats);
}